// round 13
// baseline (speedup 1.0000x reference)
#include <cuda_runtime.h>
#include <cuda_bf16.h>
#include <cstdint>
#include <cstddef>

// ---------------------------------------------------------------------------
// GAT_29437705846970: 4-layer GATConv + residual projection.
// R13: alpha (h·a_s, h·a_d) fused into GEMM epilogue as deterministic
//      per-(by,wn) partials; alpha_kernel deleted. fused_agg sums partials.
// R12: hi/lo bf16 split at smem-fill; inner loop pure LDS+mma.
// ---------------------------------------------------------------------------

constexpr int N_NODES = 50000;
constexpr int N_EDGES = 800000;
constexpr int TOT_E   = N_EDGES + N_NODES;
constexpr float NEG_SLOPE = 0.2f;

// ---- scratch (device globals) ---------------------------------------------
__device__ float g_h  [(size_t)N_NODES * 96];
__device__ float g_res[(size_t)N_NODES * 96];
__device__ float g_x  [(size_t)N_NODES * 96];
__device__ float g_asp[(size_t)6 * N_NODES];   // alpha_src partials (by*2+wn)
__device__ float g_adp[(size_t)6 * N_NODES];   // alpha_dst partials
__device__ int   g_src [TOT_E];
__device__ int   g_dst [TOT_E];
__device__ int   g_deg [N_NODES];
__device__ int   g_rowptr[N_NODES];
__device__ int   g_cursor[N_NODES];
__device__ int   g_csr_src[TOT_E];
__device__ int   g_total;
__device__ int   g_ei_is64;

// ---------------------------------------------------------------------------
// detect dtype (parallel probe, block 0) + zero g_deg + zero g_total
// ---------------------------------------------------------------------------
__global__ void detect_and_zero(const int* __restrict__ w) {
    int i = blockIdx.x * blockDim.x + threadIdx.x;
    if (i < N_NODES) g_deg[i] = 0;
    if (i == 0) g_total = 0;
    if (blockIdx.x == 0) {
        int ok = 1;
#pragma unroll
        for (int j = 0; j < 8; j++) {
            int idx = 1 + 2 * (threadIdx.x * 8 + j);   // odd words, < 4096
            if (w[idx] != 0) ok = 0;
        }
        int all = __syncthreads_and(ok);
        if (threadIdx.x == 0) g_ei_is64 = all;
    }
}

// ---------------------------------------------------------------------------
// decode edges (int32/int64, clamped), append self loops, count degrees
// ---------------------------------------------------------------------------
__global__ void prep_edges_count(const void* __restrict__ eiv) {
    int i = blockIdx.x * blockDim.x + threadIdx.x;
    if (i >= TOT_E) return;
    int s, d;
    if (i < N_EDGES) {
        long long sl, dl;
        if (g_ei_is64) {
            const long long* e64 = (const long long*)eiv;
            sl = e64[i];
            dl = e64[(size_t)N_EDGES + i];
        } else {
            const int* e32 = (const int*)eiv;
            sl = e32[i];
            dl = e32[(size_t)N_EDGES + i];
        }
        sl = sl < 0 ? 0 : (sl >= N_NODES ? N_NODES - 1 : sl);
        dl = dl < 0 ? 0 : (dl >= N_NODES ? N_NODES - 1 : dl);
        s = (int)sl; d = (int)dl;
    } else {
        s = d = i - N_EDGES;
    }
    g_src[i] = s;
    g_dst[i] = d;
    atomicAdd(&g_deg[d], 1);
}

// ---------------------------------------------------------------------------
// order-free segment allocation: block-scan degrees, one atomic per block.
// ---------------------------------------------------------------------------
__global__ void __launch_bounds__(256) assign_offsets() {
    __shared__ int warpsum[8];
    __shared__ int basesh;
    int i = blockIdx.x * 256 + threadIdx.x;
    int lane = threadIdx.x & 31, w = threadIdx.x >> 5;
    int deg = (i < N_NODES) ? g_deg[i] : 0;

    int p = deg;
#pragma unroll
    for (int o = 1; o < 32; o <<= 1) {
        int v = __shfl_up_sync(0xffffffffu, p, o);
        if (lane >= o) p += v;
    }
    if (lane == 31) warpsum[w] = p;
    __syncthreads();
    if (w == 0) {
        int s = (lane < 8) ? warpsum[lane] : 0;
#pragma unroll
        for (int o = 1; o < 8; o <<= 1) {
            int v = __shfl_up_sync(0xffffffffu, s, o);
            if (lane >= o) s += v;
        }
        if (lane < 8) warpsum[lane] = s;
        if (lane == 7) basesh = atomicAdd(&g_total, s);
    }
    __syncthreads();
    if (i < N_NODES) {
        int off = basesh + (w > 0 ? warpsum[w - 1] : 0) + p - deg;
        g_rowptr[i] = off;
        g_cursor[i] = off;
    }
}

__global__ void scatter_edges() {
    int i = blockIdx.x * blockDim.x + threadIdx.x;
    if (i >= TOT_E) return;
    int pos = atomicAdd(&g_cursor[g_dst[i]], 1);
    g_csr_src[pos] = g_src[i];
}

// ---------------------------------------------------------------------------
// 3x-bf16-split tensor-core dual GEMM: g_h = x@W, g_res = x@R.
// hi/lo split once at smem-fill; inner loop pure LDS+mma.
// Epilogue also emits alpha partials: g_asp/g_adp[(by*2+wn)][row] =
//   sum over this warp's 16 cols of h[row][c]*a_{s,d}[c]   (deterministic).
// ---------------------------------------------------------------------------
__device__ __forceinline__ void mma_bf16(float c[4],
    uint32_t a0, uint32_t a1, uint32_t a2, uint32_t a3,
    uint32_t b0, uint32_t b1) {
    asm volatile(
        "mma.sync.aligned.m16n8k16.row.col.f32.bf16.bf16.f32 "
        "{%0,%1,%2,%3}, {%4,%5,%6,%7}, {%8,%9}, {%0,%1,%2,%3};"
        : "+f"(c[0]), "+f"(c[1]), "+f"(c[2]), "+f"(c[3])
        : "r"(a0), "r"(a1), "r"(a2), "r"(a3), "r"(b0), "r"(b1));
}

__device__ __forceinline__ void split2(float f0, float f1,
                                       uint32_t& hi, uint32_t& lo) {
    __nv_bfloat16 h0 = __float2bfloat16_rn(f0);
    __nv_bfloat16 h1 = __float2bfloat16_rn(f1);
    __nv_bfloat16 l0 = __float2bfloat16_rn(f0 - __bfloat162float(h0));
    __nv_bfloat16 l1 = __float2bfloat16_rn(f1 - __bfloat162float(h1));
    hi = (uint32_t)__bfloat16_as_ushort(h0) |
         ((uint32_t)__bfloat16_as_ushort(h1) << 16);
    lo = (uint32_t)__bfloat16_as_ushort(l0) |
         ((uint32_t)__bfloat16_as_ushort(l1) << 16);
}

template <int DI, int DO, bool SRC_GX>
__global__ void __launch_bounds__(128)
gemm_dual_tc(const float* __restrict__ xarg,
             const float* __restrict__ W,
             const float* __restrict__ Rm,
             const float* __restrict__ a_s,
             const float* __restrict__ a_d) {
    constexpr int BK = 32;
    constexpr int KP = BK / 2;   // 16 k-pairs per tile
    const float* __restrict__ x = SRC_GX ? (const float*)g_x : xarg;

    __shared__ uint32_t xhi[64][17], xlo[64][17];
    __shared__ uint32_t whi[KP][40], wlo[KP][40];
    __shared__ uint32_t rhi[KP][40], rlo[KP][40];

    const int tid  = threadIdx.x;
    const int warp = tid >> 5, lane = tid & 31;
    const int wm = warp & 1, wn = warp >> 1;
    const int g  = lane >> 2, tg = lane & 3;
    const int row0 = blockIdx.x * 64;
    const int col0 = blockIdx.y * 32;

    float accW[2][2][4], accR[2][2][4];
#pragma unroll
    for (int a = 0; a < 2; a++)
#pragma unroll
        for (int b = 0; b < 2; b++)
#pragma unroll
            for (int c = 0; c < 4; c++) { accW[a][b][c] = 0.f; accR[a][b][c] = 0.f; }

    for (int k0 = 0; k0 < DI; k0 += BK) {
#pragma unroll
        for (int i = 0; i < 8; i++) {
            int linear = tid + i * 128;
            int r = linear >> 4, kp = linear & 15;
            int gr = row0 + r;
            float2 v = make_float2(0.f, 0.f);
            if (gr < N_NODES)
                v = *reinterpret_cast<const float2*>(x + (size_t)gr * DI + k0 + 2 * kp);
            split2(v.x, v.y, xhi[r][kp], xlo[r][kp]);
        }
#pragma unroll
        for (int i = 0; i < 4; i++) {
            int linear = tid + i * 128;
            int kp = linear >> 5, c = linear & 31;
            int gc = col0 + c;
            float w0 = 0.f, w1 = 0.f, r0 = 0.f, r1 = 0.f;
            if (gc < DO) {
                size_t base = (size_t)(k0 + 2 * kp) * DO + gc;
                w0 = W [base]; w1 = W [base + DO];
                r0 = Rm[base]; r1 = Rm[base + DO];
            }
            split2(w0, w1, whi[kp][c], wlo[kp][c]);
            split2(r0, r1, rhi[kp][c], rlo[kp][c]);
        }
        __syncthreads();

#pragma unroll
        for (int ks2 = 0; ks2 < KP; ks2 += 8) {
            uint32_t ahi[2][4], alo[2][4];
#pragma unroll
            for (int mt = 0; mt < 2; mt++) {
                int rb = wm * 32 + mt * 16;
                ahi[mt][0] = xhi[rb + g    ][ks2 + tg    ];
                alo[mt][0] = xlo[rb + g    ][ks2 + tg    ];
                ahi[mt][1] = xhi[rb + g + 8][ks2 + tg    ];
                alo[mt][1] = xlo[rb + g + 8][ks2 + tg    ];
                ahi[mt][2] = xhi[rb + g    ][ks2 + tg + 4];
                alo[mt][2] = xlo[rb + g    ][ks2 + tg + 4];
                ahi[mt][3] = xhi[rb + g + 8][ks2 + tg + 4];
                alo[mt][3] = xlo[rb + g + 8][ks2 + tg + 4];
            }
#pragma unroll
            for (int h = 0; h < 2; h++) {
                int nb = wn * 16 + h * 8 + g;
                uint32_t wh0 = whi[ks2 + tg    ][nb];
                uint32_t wh1 = whi[ks2 + tg + 4][nb];
                uint32_t wl0 = wlo[ks2 + tg    ][nb];
                uint32_t wl1 = wlo[ks2 + tg + 4][nb];
                uint32_t rh0 = rhi[ks2 + tg    ][nb];
                uint32_t rh1 = rhi[ks2 + tg + 4][nb];
                uint32_t rl0 = rlo[ks2 + tg    ][nb];
                uint32_t rl1 = rlo[ks2 + tg + 4][nb];
#pragma unroll
                for (int mt = 0; mt < 2; mt++) {
                    mma_bf16(accW[mt][h], ahi[mt][0], ahi[mt][1], ahi[mt][2], ahi[mt][3], wh0, wh1);
                    mma_bf16(accW[mt][h], alo[mt][0], alo[mt][1], alo[mt][2], alo[mt][3], wh0, wh1);
                    mma_bf16(accW[mt][h], ahi[mt][0], ahi[mt][1], ahi[mt][2], ahi[mt][3], wl0, wl1);
                    mma_bf16(accR[mt][h], ahi[mt][0], ahi[mt][1], ahi[mt][2], ahi[mt][3], rh0, rh1);
                    mma_bf16(accR[mt][h], alo[mt][0], alo[mt][1], alo[mt][2], alo[mt][3], rh0, rh1);
                    mma_bf16(accR[mt][h], ahi[mt][0], ahi[mt][1], ahi[mt][2], ahi[mt][3], rl0, rl1);
                }
            }
        }
        __syncthreads();
    }

    // ---- store h / res tiles ----
#pragma unroll
    for (int mt = 0; mt < 2; mt++)
#pragma unroll
        for (int h = 0; h < 2; h++) {
            int r0 = row0 + wm * 32 + mt * 16 + g;
            int c0 = col0 + wn * 16 + h * 8 + 2 * tg;
            if (c0 < DO) {
                if (r0 < N_NODES) {
                    g_h  [(size_t)r0 * DO + c0    ] = accW[mt][h][0];
                    g_h  [(size_t)r0 * DO + c0 + 1] = accW[mt][h][1];
                    g_res[(size_t)r0 * DO + c0    ] = accR[mt][h][0];
                    g_res[(size_t)r0 * DO + c0 + 1] = accR[mt][h][1];
                }
                int r1 = r0 + 8;
                if (r1 < N_NODES) {
                    g_h  [(size_t)r1 * DO + c0    ] = accW[mt][h][2];
                    g_h  [(size_t)r1 * DO + c0 + 1] = accW[mt][h][3];
                    g_res[(size_t)r1 * DO + c0    ] = accR[mt][h][2];
                    g_res[(size_t)r1 * DO + c0 + 1] = accR[mt][h][3];
                }
            }
        }

    // ---- fused alpha partials (deterministic, no atomics) ----
    float ps[2][2] = {{0.f, 0.f}, {0.f, 0.f}};
    float pd[2][2] = {{0.f, 0.f}, {0.f, 0.f}};
#pragma unroll
    for (int mt = 0; mt < 2; mt++)
#pragma unroll
        for (int h = 0; h < 2; h++) {
            int c0 = col0 + wn * 16 + h * 8 + 2 * tg;
            float as0 = 0.f, as1 = 0.f, ad0 = 0.f, ad1 = 0.f;
            if (c0 < DO) { as0 = a_s[c0]; as1 = a_s[c0 + 1];
                           ad0 = a_d[c0]; ad1 = a_d[c0 + 1]; }
            ps[mt][0] += accW[mt][h][0] * as0 + accW[mt][h][1] * as1;
            ps[mt][1] += accW[mt][h][2] * as0 + accW[mt][h][3] * as1;
            pd[mt][0] += accW[mt][h][0] * ad0 + accW[mt][h][1] * ad1;
            pd[mt][1] += accW[mt][h][2] * ad0 + accW[mt][h][3] * ad1;
        }
    // reduce across the 4-lane tg group (lane bits 0..1)
#pragma unroll
    for (int o = 1; o < 4; o <<= 1)
#pragma unroll
        for (int mt = 0; mt < 2; mt++) {
            ps[mt][0] += __shfl_xor_sync(0xffffffffu, ps[mt][0], o);
            ps[mt][1] += __shfl_xor_sync(0xffffffffu, ps[mt][1], o);
            pd[mt][0] += __shfl_xor_sync(0xffffffffu, pd[mt][0], o);
            pd[mt][1] += __shfl_xor_sync(0xffffffffu, pd[mt][1], o);
        }
    if (tg == 0) {
        size_t pb = (size_t)(blockIdx.y * 2 + wn) * N_NODES;
#pragma unroll
        for (int mt = 0; mt < 2; mt++) {
            int r0 = row0 + wm * 32 + mt * 16 + g;
            if (r0 < N_NODES)     { g_asp[pb + r0]     = ps[mt][0]; g_adp[pb + r0]     = pd[mt][0]; }
            if (r0 + 8 < N_NODES) { g_asp[pb + r0 + 8] = ps[mt][1]; g_adp[pb + r0 + 8] = pd[mt][1]; }
        }
    }
}

// ---------------------------------------------------------------------------
// alpha partial sum helper (NP = 2 * gridDim.y of the gemm)
// ---------------------------------------------------------------------------
template <int NP>
__device__ __forceinline__ float sum_parts(const float* __restrict__ base, int s) {
    float v = base[s];
#pragma unroll
    for (int p = 1; p < NP; p++) v += base[(size_t)p * N_NODES + s];
    return v;
}

// ---------------------------------------------------------------------------
// Fused softmax + aggregate + relu + residual, one warp per dst node.
// ---------------------------------------------------------------------------
template <int DO, bool DST_GX>
__global__ void __launch_bounds__(256)
fused_agg(float* __restrict__ xout) {
    constexpr int TILE  = 64;
    constexpr int WARPS = 8;
    constexpr int RI    = (DO + 31) / 32;
    constexpr int NP    = 2 * ((DO + 31) / 32);   // alpha partial count
    __shared__ float sw  [WARPS][TILE];
    __shared__ int   ssrc[WARPS][TILE];

    const int warp = threadIdx.x >> 5;
    const int lane = threadIdx.x & 31;
    const int node = blockIdx.x * WARPS + warp;
    if (node >= N_NODES) return;

    const int beg = g_rowptr[node];
    const int deg = g_deg[node];
    const int end = beg + deg;
    const float adst = sum_parts<NP>(g_adp, node);

    float acc[RI];
#pragma unroll
    for (int i = 0; i < RI; i++) acc[i] = 0.f;

    if (deg <= TILE) {
        float mx = -3.4e38f;
        for (int e = lane; e < deg; e += 32) {
            int s = g_csr_src[beg + e];
            float v = sum_parts<NP>(g_asp, s) + adst;
            v = (v > 0.f) ? v : NEG_SLOPE * v;
            ssrc[warp][e] = s;
            sw  [warp][e] = v;
            mx = fmaxf(mx, v);
        }
#pragma unroll
        for (int o = 16; o; o >>= 1) mx = fmaxf(mx, __shfl_xor_sync(0xffffffffu, mx, o));

        float sum = 0.f;
        __syncwarp();
        for (int e = lane; e < deg; e += 32) {
            float w = __expf(sw[warp][e] - mx);
            sw[warp][e] = w;
            sum += w;
        }
#pragma unroll
        for (int o = 16; o; o >>= 1) sum += __shfl_xor_sync(0xffffffffu, sum, o);
        const float inv = 1.f / sum;

        __syncwarp();
        for (int e = 0; e < deg; e++) {
            const float a = sw[warp][e] * inv;
            const float* hp = g_h + (size_t)ssrc[warp][e] * DO;
#pragma unroll
            for (int i = 0; i < RI; i++) {
                int c = lane + 32 * i;
                if (c < DO) acc[i] = fmaf(hp[c], a, acc[i]);
            }
        }
    } else {
        float mx = -3.4e38f;
        for (int e = beg + lane; e < end; e += 32) {
            float v = sum_parts<NP>(g_asp, g_csr_src[e]) + adst;
            v = (v > 0.f) ? v : NEG_SLOPE * v;
            mx = fmaxf(mx, v);
        }
#pragma unroll
        for (int o = 16; o; o >>= 1) mx = fmaxf(mx, __shfl_xor_sync(0xffffffffu, mx, o));

        float sum = 0.f;
        for (int e = beg + lane; e < end; e += 32) {
            float v = sum_parts<NP>(g_asp, g_csr_src[e]) + adst;
            v = (v > 0.f) ? v : NEG_SLOPE * v;
            sum += __expf(v - mx);
        }
#pragma unroll
        for (int o = 16; o; o >>= 1) sum += __shfl_xor_sync(0xffffffffu, sum, o);
        const float inv = 1.f / sum;

        for (int t0 = beg; t0 < end; t0 += TILE) {
            const int cnt = min(TILE, end - t0);
            for (int e = lane; e < cnt; e += 32) {
                int s = g_csr_src[t0 + e];
                float v = sum_parts<NP>(g_asp, s) + adst;
                v = (v > 0.f) ? v : NEG_SLOPE * v;
                sw  [warp][e] = __expf(v - mx) * inv;
                ssrc[warp][e] = s;
            }
            __syncwarp();
            for (int e = 0; e < cnt; e++) {
                const float a = sw[warp][e];
                const float* hp = g_h + (size_t)ssrc[warp][e] * DO;
#pragma unroll
                for (int i = 0; i < RI; i++) {
                    int c = lane + 32 * i;
                    if (c < DO) acc[i] = fmaf(hp[c], a, acc[i]);
                }
            }
            __syncwarp();
        }
    }

    const size_t o = (size_t)node * DO;
#pragma unroll
    for (int i = 0; i < RI; i++) {
        int c = lane + 32 * i;
        if (c < DO) {
            float v = acc[i] > 0.f ? acc[i] : 0.f;
            v += g_res[o + c];
            if (DST_GX) g_x[o + c]  = v;
            else        xout[o + c] = v;
        }
    }
}

// ---------------------------------------------------------------------------
// host side
// ---------------------------------------------------------------------------
template <int DI, int DO, bool SRC_GX, bool DST_GX>
static void run_layer(const float* xin,
                      const float* Wp, const float* asp, const float* adp,
                      const float* Rp, float* xout) {
    dim3 grid((N_NODES + 63) / 64, (DO + 31) / 32);
    gemm_dual_tc<DI, DO, SRC_GX><<<grid, 128>>>(xin, Wp, Rp, asp, adp);
    fused_agg<DO, DST_GX><<<(N_NODES + 7) / 8, 256>>>(xout);
}

extern "C" void kernel_launch(void* const* d_in, const int* in_sizes, int n_in,
                              void* d_out, int out_size) {
    // ---- input layout detection (size-signature match) ----
    const int SZ_X  = N_NODES * 256;
    const int SZ_EI = 2 * N_EDGES;
    const int szW[4] = {256 * 96, 96 * 96, 96 * 96, 96 * 48};
    const int szA[4] = {96, 96, 96, 48};

    int ins[18]; int p = 0;
    ins[p++] = SZ_X; ins[p++] = SZ_EI;
    for (int i = 0; i < 4; i++) {
        ins[p++] = szW[i]; ins[p++] = szA[i]; ins[p++] = szA[i]; ins[p++] = szW[i];
    }
    int alp[18]; p = 0;
    for (int i = 0; i < 4; i++) alp[p++] = szW[i];
    for (int i = 0; i < 4; i++) alp[p++] = szW[i];
    for (int i = 0; i < 4; i++) { alp[p++] = szA[i]; alp[p++] = szA[i]; }
    alp[p++] = SZ_EI; alp[p++] = SZ_X;

    bool ins_ok = (n_in == 18), alp_ok = (n_in == 18);
    for (int i = 0; i < 18 && i < n_in; i++) {
        if (in_sizes[i] != ins[i]) ins_ok = false;
        if (in_sizes[i] != alp[i]) alp_ok = false;
    }

    const float* x0; const void* ei;
    const float *W[4], *AS[4], *AD[4], *R[4];

    if (ins_ok || !alp_ok) {
        x0 = (const float*)d_in[0];
        ei = d_in[1];
        for (int i = 0; i < 4; i++) {
            W [i] = (const float*)d_in[2 + 4 * i];
            AS[i] = (const float*)d_in[3 + 4 * i];
            AD[i] = (const float*)d_in[4 + 4 * i];
            R [i] = (const float*)d_in[5 + 4 * i];
        }
    } else {
        for (int i = 0; i < 4; i++) {
            R [i] = (const float*)d_in[i];
            W [i] = (const float*)d_in[4 + i];
            AD[i] = (const float*)d_in[8 + 2 * i];
            AS[i] = (const float*)d_in[9 + 2 * i];
        }
        ei = d_in[16];
        x0 = (const float*)d_in[17];
    }

    // ---- one-time graph preprocessing ----
    detect_and_zero<<<(N_NODES + 255) / 256, 256>>>((const int*)ei);
    prep_edges_count<<<(TOT_E + 255) / 256, 256>>>(ei);
    assign_offsets<<<(N_NODES + 255) / 256, 256>>>();
    scatter_edges<<<(TOT_E + 255) / 256, 256>>>();

    // ---- 4 GAT layers ----
    run_layer<256, 96, false, true >(x0,      W[0], AS[0], AD[0], R[0], nullptr);
    run_layer< 96, 96, true,  true >(nullptr, W[1], AS[1], AD[1], R[1], nullptr);
    run_layer< 96, 96, true,  true >(nullptr, W[2], AS[2], AD[2], R[2], nullptr);
    run_layer< 96, 48, true,  false>(nullptr, W[3], AS[3], AD[3], R[3], (float*)d_out);
}

// round 15
// speedup vs baseline: 1.0733x; 1.0733x over previous
#include <cuda_runtime.h>
#include <cuda_bf16.h>
#include <cstdint>
#include <cstddef>

// ---------------------------------------------------------------------------
// GAT_29437705846970: 4-layer GATConv + residual projection.
// R14: alpha partials from GEMM epilogue are collapsed by a tiny reduce
//      kernel into dense g_asrc/g_adst; fused_agg reads 1 value per edge
//      (R12 form). Fixes R13's 6x per-edge gather regression.
// R15: identical resubmit of R14 (round 14 bench was an infra failure).
// ---------------------------------------------------------------------------

constexpr int N_NODES = 50000;
constexpr int N_EDGES = 800000;
constexpr int TOT_E   = N_EDGES + N_NODES;
constexpr float NEG_SLOPE = 0.2f;

// ---- scratch (device globals) ---------------------------------------------
__device__ float g_h  [(size_t)N_NODES * 96];
__device__ float g_res[(size_t)N_NODES * 96];
__device__ float g_x  [(size_t)N_NODES * 96];
__device__ float g_asp[(size_t)6 * N_NODES];   // alpha_src partials (by*2+wn)
__device__ float g_adp[(size_t)6 * N_NODES];   // alpha_dst partials
__device__ float g_asrc[N_NODES];
__device__ float g_adst[N_NODES];
__device__ int   g_src [TOT_E];
__device__ int   g_dst [TOT_E];
__device__ int   g_deg [N_NODES];
__device__ int   g_rowptr[N_NODES];
__device__ int   g_cursor[N_NODES];
__device__ int   g_csr_src[TOT_E];
__device__ int   g_total;
__device__ int   g_ei_is64;

// ---------------------------------------------------------------------------
// detect dtype (parallel probe, block 0) + zero g_deg + zero g_total
// ---------------------------------------------------------------------------
__global__ void detect_and_zero(const int* __restrict__ w) {
    int i = blockIdx.x * blockDim.x + threadIdx.x;
    if (i < N_NODES) g_deg[i] = 0;
    if (i == 0) g_total = 0;
    if (blockIdx.x == 0) {
        int ok = 1;
#pragma unroll
        for (int j = 0; j < 8; j++) {
            int idx = 1 + 2 * (threadIdx.x * 8 + j);   // odd words, < 4096
            if (w[idx] != 0) ok = 0;
        }
        int all = __syncthreads_and(ok);
        if (threadIdx.x == 0) g_ei_is64 = all;
    }
}

// ---------------------------------------------------------------------------
// decode edges (int32/int64, clamped), append self loops, count degrees
// ---------------------------------------------------------------------------
__global__ void prep_edges_count(const void* __restrict__ eiv) {
    int i = blockIdx.x * blockDim.x + threadIdx.x;
    if (i >= TOT_E) return;
    int s, d;
    if (i < N_EDGES) {
        long long sl, dl;
        if (g_ei_is64) {
            const long long* e64 = (const long long*)eiv;
            sl = e64[i];
            dl = e64[(size_t)N_EDGES + i];
        } else {
            const int* e32 = (const int*)eiv;
            sl = e32[i];
            dl = e32[(size_t)N_EDGES + i];
        }
        sl = sl < 0 ? 0 : (sl >= N_NODES ? N_NODES - 1 : sl);
        dl = dl < 0 ? 0 : (dl >= N_NODES ? N_NODES - 1 : dl);
        s = (int)sl; d = (int)dl;
    } else {
        s = d = i - N_EDGES;
    }
    g_src[i] = s;
    g_dst[i] = d;
    atomicAdd(&g_deg[d], 1);
}

// ---------------------------------------------------------------------------
// order-free segment allocation: block-scan degrees, one atomic per block.
// ---------------------------------------------------------------------------
__global__ void __launch_bounds__(256) assign_offsets() {
    __shared__ int warpsum[8];
    __shared__ int basesh;
    int i = blockIdx.x * 256 + threadIdx.x;
    int lane = threadIdx.x & 31, w = threadIdx.x >> 5;
    int deg = (i < N_NODES) ? g_deg[i] : 0;

    int p = deg;
#pragma unroll
    for (int o = 1; o < 32; o <<= 1) {
        int v = __shfl_up_sync(0xffffffffu, p, o);
        if (lane >= o) p += v;
    }
    if (lane == 31) warpsum[w] = p;
    __syncthreads();
    if (w == 0) {
        int s = (lane < 8) ? warpsum[lane] : 0;
#pragma unroll
        for (int o = 1; o < 8; o <<= 1) {
            int v = __shfl_up_sync(0xffffffffu, s, o);
            if (lane >= o) s += v;
        }
        if (lane < 8) warpsum[lane] = s;
        if (lane == 7) basesh = atomicAdd(&g_total, s);
    }
    __syncthreads();
    if (i < N_NODES) {
        int off = basesh + (w > 0 ? warpsum[w - 1] : 0) + p - deg;
        g_rowptr[i] = off;
        g_cursor[i] = off;
    }
}

__global__ void scatter_edges() {
    int i = blockIdx.x * blockDim.x + threadIdx.x;
    if (i >= TOT_E) return;
    int pos = atomicAdd(&g_cursor[g_dst[i]], 1);
    g_csr_src[pos] = g_src[i];
}

// ---------------------------------------------------------------------------
// 3x-bf16-split tensor-core dual GEMM: g_h = x@W, g_res = x@R.
// hi/lo split once at smem-fill; inner loop pure LDS+mma.
// Epilogue emits deterministic alpha partials g_asp/g_adp[(by*2+wn)][row].
// ---------------------------------------------------------------------------
__device__ __forceinline__ void mma_bf16(float c[4],
    uint32_t a0, uint32_t a1, uint32_t a2, uint32_t a3,
    uint32_t b0, uint32_t b1) {
    asm volatile(
        "mma.sync.aligned.m16n8k16.row.col.f32.bf16.bf16.f32 "
        "{%0,%1,%2,%3}, {%4,%5,%6,%7}, {%8,%9}, {%0,%1,%2,%3};"
        : "+f"(c[0]), "+f"(c[1]), "+f"(c[2]), "+f"(c[3])
        : "r"(a0), "r"(a1), "r"(a2), "r"(a3), "r"(b0), "r"(b1));
}

__device__ __forceinline__ void split2(float f0, float f1,
                                       uint32_t& hi, uint32_t& lo) {
    __nv_bfloat16 h0 = __float2bfloat16_rn(f0);
    __nv_bfloat16 h1 = __float2bfloat16_rn(f1);
    __nv_bfloat16 l0 = __float2bfloat16_rn(f0 - __bfloat162float(h0));
    __nv_bfloat16 l1 = __float2bfloat16_rn(f1 - __bfloat162float(h1));
    hi = (uint32_t)__bfloat16_as_ushort(h0) |
         ((uint32_t)__bfloat16_as_ushort(h1) << 16);
    lo = (uint32_t)__bfloat16_as_ushort(l0) |
         ((uint32_t)__bfloat16_as_ushort(l1) << 16);
}

template <int DI, int DO, bool SRC_GX>
__global__ void __launch_bounds__(128)
gemm_dual_tc(const float* __restrict__ xarg,
             const float* __restrict__ W,
             const float* __restrict__ Rm,
             const float* __restrict__ a_s,
             const float* __restrict__ a_d) {
    constexpr int BK = 32;
    constexpr int KP = BK / 2;   // 16 k-pairs per tile
    const float* __restrict__ x = SRC_GX ? (const float*)g_x : xarg;

    __shared__ uint32_t xhi[64][17], xlo[64][17];
    __shared__ uint32_t whi[KP][40], wlo[KP][40];
    __shared__ uint32_t rhi[KP][40], rlo[KP][40];

    const int tid  = threadIdx.x;
    const int warp = tid >> 5, lane = tid & 31;
    const int wm = warp & 1, wn = warp >> 1;
    const int g  = lane >> 2, tg = lane & 3;
    const int row0 = blockIdx.x * 64;
    const int col0 = blockIdx.y * 32;

    float accW[2][2][4], accR[2][2][4];
#pragma unroll
    for (int a = 0; a < 2; a++)
#pragma unroll
        for (int b = 0; b < 2; b++)
#pragma unroll
            for (int c = 0; c < 4; c++) { accW[a][b][c] = 0.f; accR[a][b][c] = 0.f; }

    for (int k0 = 0; k0 < DI; k0 += BK) {
#pragma unroll
        for (int i = 0; i < 8; i++) {
            int linear = tid + i * 128;
            int r = linear >> 4, kp = linear & 15;
            int gr = row0 + r;
            float2 v = make_float2(0.f, 0.f);
            if (gr < N_NODES)
                v = *reinterpret_cast<const float2*>(x + (size_t)gr * DI + k0 + 2 * kp);
            split2(v.x, v.y, xhi[r][kp], xlo[r][kp]);
        }
#pragma unroll
        for (int i = 0; i < 4; i++) {
            int linear = tid + i * 128;
            int kp = linear >> 5, c = linear & 31;
            int gc = col0 + c;
            float w0 = 0.f, w1 = 0.f, r0 = 0.f, r1 = 0.f;
            if (gc < DO) {
                size_t base = (size_t)(k0 + 2 * kp) * DO + gc;
                w0 = W [base]; w1 = W [base + DO];
                r0 = Rm[base]; r1 = Rm[base + DO];
            }
            split2(w0, w1, whi[kp][c], wlo[kp][c]);
            split2(r0, r1, rhi[kp][c], rlo[kp][c]);
        }
        __syncthreads();

#pragma unroll
        for (int ks2 = 0; ks2 < KP; ks2 += 8) {
            uint32_t ahi[2][4], alo[2][4];
#pragma unroll
            for (int mt = 0; mt < 2; mt++) {
                int rb = wm * 32 + mt * 16;
                ahi[mt][0] = xhi[rb + g    ][ks2 + tg    ];
                alo[mt][0] = xlo[rb + g    ][ks2 + tg    ];
                ahi[mt][1] = xhi[rb + g + 8][ks2 + tg    ];
                alo[mt][1] = xlo[rb + g + 8][ks2 + tg    ];
                ahi[mt][2] = xhi[rb + g    ][ks2 + tg + 4];
                alo[mt][2] = xlo[rb + g    ][ks2 + tg + 4];
                ahi[mt][3] = xhi[rb + g + 8][ks2 + tg + 4];
                alo[mt][3] = xlo[rb + g + 8][ks2 + tg + 4];
            }
#pragma unroll
            for (int h = 0; h < 2; h++) {
                int nb = wn * 16 + h * 8 + g;
                uint32_t wh0 = whi[ks2 + tg    ][nb];
                uint32_t wh1 = whi[ks2 + tg + 4][nb];
                uint32_t wl0 = wlo[ks2 + tg    ][nb];
                uint32_t wl1 = wlo[ks2 + tg + 4][nb];
                uint32_t rh0 = rhi[ks2 + tg    ][nb];
                uint32_t rh1 = rhi[ks2 + tg + 4][nb];
                uint32_t rl0 = rlo[ks2 + tg    ][nb];
                uint32_t rl1 = rlo[ks2 + tg + 4][nb];
#pragma unroll
                for (int mt = 0; mt < 2; mt++) {
                    mma_bf16(accW[mt][h], ahi[mt][0], ahi[mt][1], ahi[mt][2], ahi[mt][3], wh0, wh1);
                    mma_bf16(accW[mt][h], alo[mt][0], alo[mt][1], alo[mt][2], alo[mt][3], wh0, wh1);
                    mma_bf16(accW[mt][h], ahi[mt][0], ahi[mt][1], ahi[mt][2], ahi[mt][3], wl0, wl1);
                    mma_bf16(accR[mt][h], ahi[mt][0], ahi[mt][1], ahi[mt][2], ahi[mt][3], rh0, rh1);
                    mma_bf16(accR[mt][h], alo[mt][0], alo[mt][1], alo[mt][2], alo[mt][3], rh0, rh1);
                    mma_bf16(accR[mt][h], ahi[mt][0], ahi[mt][1], ahi[mt][2], ahi[mt][3], rl0, rl1);
                }
            }
        }
        __syncthreads();
    }

    // ---- store h / res tiles ----
#pragma unroll
    for (int mt = 0; mt < 2; mt++)
#pragma unroll
        for (int h = 0; h < 2; h++) {
            int r0 = row0 + wm * 32 + mt * 16 + g;
            int c0 = col0 + wn * 16 + h * 8 + 2 * tg;
            if (c0 < DO) {
                if (r0 < N_NODES) {
                    g_h  [(size_t)r0 * DO + c0    ] = accW[mt][h][0];
                    g_h  [(size_t)r0 * DO + c0 + 1] = accW[mt][h][1];
                    g_res[(size_t)r0 * DO + c0    ] = accR[mt][h][0];
                    g_res[(size_t)r0 * DO + c0 + 1] = accR[mt][h][1];
                }
                int r1 = r0 + 8;
                if (r1 < N_NODES) {
                    g_h  [(size_t)r1 * DO + c0    ] = accW[mt][h][2];
                    g_h  [(size_t)r1 * DO + c0 + 1] = accW[mt][h][3];
                    g_res[(size_t)r1 * DO + c0    ] = accR[mt][h][2];
                    g_res[(size_t)r1 * DO + c0 + 1] = accR[mt][h][3];
                }
            }
        }

    // ---- fused alpha partials (deterministic, no atomics) ----
    float ps[2][2] = {{0.f, 0.f}, {0.f, 0.f}};
    float pd[2][2] = {{0.f, 0.f}, {0.f, 0.f}};
#pragma unroll
    for (int mt = 0; mt < 2; mt++)
#pragma unroll
        for (int h = 0; h < 2; h++) {
            int c0 = col0 + wn * 16 + h * 8 + 2 * tg;
            float as0 = 0.f, as1 = 0.f, ad0 = 0.f, ad1 = 0.f;
            if (c0 < DO) { as0 = a_s[c0]; as1 = a_s[c0 + 1];
                           ad0 = a_d[c0]; ad1 = a_d[c0 + 1]; }
            ps[mt][0] += accW[mt][h][0] * as0 + accW[mt][h][1] * as1;
            ps[mt][1] += accW[mt][h][2] * as0 + accW[mt][h][3] * as1;
            pd[mt][0] += accW[mt][h][0] * ad0 + accW[mt][h][1] * ad1;
            pd[mt][1] += accW[mt][h][2] * ad0 + accW[mt][h][3] * ad1;
        }
#pragma unroll
    for (int o = 1; o < 4; o <<= 1)
#pragma unroll
        for (int mt = 0; mt < 2; mt++) {
            ps[mt][0] += __shfl_xor_sync(0xffffffffu, ps[mt][0], o);
            ps[mt][1] += __shfl_xor_sync(0xffffffffu, ps[mt][1], o);
            pd[mt][0] += __shfl_xor_sync(0xffffffffu, pd[mt][0], o);
            pd[mt][1] += __shfl_xor_sync(0xffffffffu, pd[mt][1], o);
        }
    if (tg == 0) {
        size_t pb = (size_t)(blockIdx.y * 2 + wn) * N_NODES;
#pragma unroll
        for (int mt = 0; mt < 2; mt++) {
            int r0 = row0 + wm * 32 + mt * 16 + g;
            if (r0 < N_NODES)     { g_asp[pb + r0]     = ps[mt][0]; g_adp[pb + r0]     = pd[mt][0]; }
            if (r0 + 8 < N_NODES) { g_asp[pb + r0 + 8] = ps[mt][1]; g_adp[pb + r0 + 8] = pd[mt][1]; }
        }
    }
}

// ---------------------------------------------------------------------------
// reduce alpha partials -> dense g_asrc/g_adst  (coalesced, ~3us)
// ---------------------------------------------------------------------------
template <int NP>
__global__ void reduce_alpha() {
    int i = blockIdx.x * blockDim.x + threadIdx.x;
    if (i >= N_NODES) return;
    float s = g_asp[i], d = g_adp[i];
#pragma unroll
    for (int p = 1; p < NP; p++) {
        s += g_asp[(size_t)p * N_NODES + i];
        d += g_adp[(size_t)p * N_NODES + i];
    }
    g_asrc[i] = s;
    g_adst[i] = d;
}

// ---------------------------------------------------------------------------
// Fused softmax + aggregate + relu + residual, one warp per dst node.
// (R12 form: single g_asrc load per edge.)
// ---------------------------------------------------------------------------
template <int DO, bool DST_GX>
__global__ void __launch_bounds__(256)
fused_agg(float* __restrict__ xout) {
    constexpr int TILE  = 64;
    constexpr int WARPS = 8;
    constexpr int RI    = (DO + 31) / 32;
    __shared__ float sw  [WARPS][TILE];
    __shared__ int   ssrc[WARPS][TILE];

    const int warp = threadIdx.x >> 5;
    const int lane = threadIdx.x & 31;
    const int node = blockIdx.x * WARPS + warp;
    if (node >= N_NODES) return;

    const int beg = g_rowptr[node];
    const int deg = g_deg[node];
    const int end = beg + deg;
    const float adst = g_adst[node];

    float acc[RI];
#pragma unroll
    for (int i = 0; i < RI; i++) acc[i] = 0.f;

    if (deg <= TILE) {
        float mx = -3.4e38f;
        for (int e = lane; e < deg; e += 32) {
            int s = g_csr_src[beg + e];
            float v = g_asrc[s] + adst;
            v = (v > 0.f) ? v : NEG_SLOPE * v;
            ssrc[warp][e] = s;
            sw  [warp][e] = v;
            mx = fmaxf(mx, v);
        }
#pragma unroll
        for (int o = 16; o; o >>= 1) mx = fmaxf(mx, __shfl_xor_sync(0xffffffffu, mx, o));

        float sum = 0.f;
        __syncwarp();
        for (int e = lane; e < deg; e += 32) {
            float w = __expf(sw[warp][e] - mx);
            sw[warp][e] = w;
            sum += w;
        }
#pragma unroll
        for (int o = 16; o; o >>= 1) sum += __shfl_xor_sync(0xffffffffu, sum, o);
        const float inv = 1.f / sum;

        __syncwarp();
        for (int e = 0; e < deg; e++) {
            const float a = sw[warp][e] * inv;
            const float* hp = g_h + (size_t)ssrc[warp][e] * DO;
#pragma unroll
            for (int i = 0; i < RI; i++) {
                int c = lane + 32 * i;
                if (c < DO) acc[i] = fmaf(hp[c], a, acc[i]);
            }
        }
    } else {
        float mx = -3.4e38f;
        for (int e = beg + lane; e < end; e += 32) {
            float v = g_asrc[g_csr_src[e]] + adst;
            v = (v > 0.f) ? v : NEG_SLOPE * v;
            mx = fmaxf(mx, v);
        }
#pragma unroll
        for (int o = 16; o; o >>= 1) mx = fmaxf(mx, __shfl_xor_sync(0xffffffffu, mx, o));

        float sum = 0.f;
        for (int e = beg + lane; e < end; e += 32) {
            float v = g_asrc[g_csr_src[e]] + adst;
            v = (v > 0.f) ? v : NEG_SLOPE * v;
            sum += __expf(v - mx);
        }
#pragma unroll
        for (int o = 16; o; o >>= 1) sum += __shfl_xor_sync(0xffffffffu, sum, o);
        const float inv = 1.f / sum;

        for (int t0 = beg; t0 < end; t0 += TILE) {
            const int cnt = min(TILE, end - t0);
            for (int e = lane; e < cnt; e += 32) {
                int s = g_csr_src[t0 + e];
                float v = g_asrc[s] + adst;
                v = (v > 0.f) ? v : NEG_SLOPE * v;
                sw  [warp][e] = __expf(v - mx) * inv;
                ssrc[warp][e] = s;
            }
            __syncwarp();
            for (int e = 0; e < cnt; e++) {
                const float a = sw[warp][e];
                const float* hp = g_h + (size_t)ssrc[warp][e] * DO;
#pragma unroll
                for (int i = 0; i < RI; i++) {
                    int c = lane + 32 * i;
                    if (c < DO) acc[i] = fmaf(hp[c], a, acc[i]);
                }
            }
            __syncwarp();
        }
    }

    const size_t o = (size_t)node * DO;
#pragma unroll
    for (int i = 0; i < RI; i++) {
        int c = lane + 32 * i;
        if (c < DO) {
            float v = acc[i] > 0.f ? acc[i] : 0.f;
            v += g_res[o + c];
            if (DST_GX) g_x[o + c]  = v;
            else        xout[o + c] = v;
        }
    }
}

// ---------------------------------------------------------------------------
// host side
// ---------------------------------------------------------------------------
template <int DI, int DO, bool SRC_GX, bool DST_GX>
static void run_layer(const float* xin,
                      const float* Wp, const float* asp, const float* adp,
                      const float* Rp, float* xout) {
    constexpr int NP = 2 * ((DO + 31) / 32);   // partial planes
    dim3 grid((N_NODES + 63) / 64, (DO + 31) / 32);
    gemm_dual_tc<DI, DO, SRC_GX><<<grid, 128>>>(xin, Wp, Rp, asp, adp);
    reduce_alpha<NP><<<(N_NODES + 255) / 256, 256>>>();
    fused_agg<DO, DST_GX><<<(N_NODES + 7) / 8, 256>>>(xout);
}

extern "C" void kernel_launch(void* const* d_in, const int* in_sizes, int n_in,
                              void* d_out, int out_size) {
    // ---- input layout detection (size-signature match) ----
    const int SZ_X  = N_NODES * 256;
    const int SZ_EI = 2 * N_EDGES;
    const int szW[4] = {256 * 96, 96 * 96, 96 * 96, 96 * 48};
    const int szA[4] = {96, 96, 96, 48};

    int ins[18]; int p = 0;
    ins[p++] = SZ_X; ins[p++] = SZ_EI;
    for (int i = 0; i < 4; i++) {
        ins[p++] = szW[i]; ins[p++] = szA[i]; ins[p++] = szA[i]; ins[p++] = szW[i];
    }
    int alp[18]; p = 0;
    for (int i = 0; i < 4; i++) alp[p++] = szW[i];
    for (int i = 0; i < 4; i++) alp[p++] = szW[i];
    for (int i = 0; i < 4; i++) { alp[p++] = szA[i]; alp[p++] = szA[i]; }
    alp[p++] = SZ_EI; alp[p++] = SZ_X;

    bool ins_ok = (n_in == 18), alp_ok = (n_in == 18);
    for (int i = 0; i < 18 && i < n_in; i++) {
        if (in_sizes[i] != ins[i]) ins_ok = false;
        if (in_sizes[i] != alp[i]) alp_ok = false;
    }

    const float* x0; const void* ei;
    const float *W[4], *AS[4], *AD[4], *R[4];

    if (ins_ok || !alp_ok) {
        x0 = (const float*)d_in[0];
        ei = d_in[1];
        for (int i = 0; i < 4; i++) {
            W [i] = (const float*)d_in[2 + 4 * i];
            AS[i] = (const float*)d_in[3 + 4 * i];
            AD[i] = (const float*)d_in[4 + 4 * i];
            R [i] = (const float*)d_in[5 + 4 * i];
        }
    } else {
        for (int i = 0; i < 4; i++) {
            R [i] = (const float*)d_in[i];
            W [i] = (const float*)d_in[4 + i];
            AD[i] = (const float*)d_in[8 + 2 * i];
            AS[i] = (const float*)d_in[9 + 2 * i];
        }
        ei = d_in[16];
        x0 = (const float*)d_in[17];
    }

    // ---- one-time graph preprocessing ----
    detect_and_zero<<<(N_NODES + 255) / 256, 256>>>((const int*)ei);
    prep_edges_count<<<(TOT_E + 255) / 256, 256>>>(ei);
    assign_offsets<<<(N_NODES + 255) / 256, 256>>>();
    scatter_edges<<<(TOT_E + 255) / 256, 256>>>();

    // ---- 4 GAT layers ----
    run_layer<256, 96, false, true >(x0,      W[0], AS[0], AD[0], R[0], nullptr);
    run_layer< 96, 96, true,  true >(nullptr, W[1], AS[1], AD[1], R[1], nullptr);
    run_layer< 96, 96, true,  true >(nullptr, W[2], AS[2], AD[2], R[2], nullptr);
    run_layer< 96, 48, true,  false>(nullptr, W[3], AS[3], AD[3], R[3], (float*)d_out);
}